// round 1
// baseline (speedup 1.0000x reference)
#include <cuda_runtime.h>
#include <cuda_bf16.h>
#include <math.h>

// Problem constants
#define BB 4
#define SS 2048
#define DD 1024
#define HH 16
#define DH 64

// ---------------------------------------------------------------------------
// Scratch (device globals — no runtime allocation allowed)
// ---------------------------------------------------------------------------
__device__ float g_qkv [(long)BB * SS * 3 * DD];   // [B,S,3D]
__device__ float g_hop [(long)BB * SS * SS];       // [B,S,S]
__device__ float g_attn[(long)BB * SS * DD];       // attention output (pre O-proj)
__device__ float g_att2[(long)BB * SS * DD];       // after O-proj
__device__ float g_x1  [(long)BB * SS * DD];       // after LN1
__device__ float g_ff1 [(long)BB * SS * 4 * DD];   // after FFN1+GELU
__device__ float g_ff2 [(long)BB * SS * DD];       // after FFN2

__device__ __forceinline__ float gelu_exact(float x) {
    return 0.5f * x * (1.0f + erff(x * 0.70710678118654752f));
}

// ---------------------------------------------------------------------------
// Generic SGEMM: C[M,N] = scale * (A[M,K] @ B[N,K]^T) + bias[N], optional GELU.
// 128x128x16 tiles, 256 threads, 8x8 per thread in split-quad layout.
// Requires M%128==0, N%128==0, K%16==0 (true for all call sites).
// causal!=0 => skip tiles with n0 > m0+127 (used for hopping matrix).
// ---------------------------------------------------------------------------
template<bool GELU>
__global__ __launch_bounds__(256)
void sgemm_bt(const float* __restrict__ A, const float* __restrict__ B,
              const float* __restrict__ bias, float* __restrict__ C,
              int M, int N, int K,
              long sA, long sB, long sC, float scale, int causal)
{
    __shared__ float As[16][132];   // A^T tile: As[k][m]
    __shared__ float Bs[16][132];   // B^T tile: Bs[k][n]

    const int tid = threadIdx.x;
    const int tx = tid & 15;
    const int ty = tid >> 4;
    const int m0 = blockIdx.y * 128;
    const int n0 = blockIdx.x * 128;

    if (causal && n0 > m0 + 127) return;

    const int z = blockIdx.z;
    A += (long)z * sA;
    B += (long)z * sB;
    C += (long)z * sC;

    float acc[2][2][4][4];
    #pragma unroll
    for (int a = 0; a < 2; a++)
        #pragma unroll
        for (int b = 0; b < 2; b++)
            #pragma unroll
            for (int i = 0; i < 4; i++)
                #pragma unroll
                for (int j = 0; j < 4; j++)
                    acc[a][b][i][j] = 0.0f;

    for (int k0 = 0; k0 < K; k0 += 16) {
        // Cooperative load: 128x16 tiles of A and B, stored transposed.
        #pragma unroll
        for (int l = 0; l < 2; l++) {
            int f   = tid * 2 + l;        // 0..511
            int row = f >> 2;             // 0..127
            int kc  = f & 3;              // float4 column 0..3
            float4 va = *(const float4*)&A[(long)(m0 + row) * K + k0 + kc * 4];
            As[kc*4+0][row] = va.x;
            As[kc*4+1][row] = va.y;
            As[kc*4+2][row] = va.z;
            As[kc*4+3][row] = va.w;
            float4 vb = *(const float4*)&B[(long)(n0 + row) * K + k0 + kc * 4];
            Bs[kc*4+0][row] = vb.x;
            Bs[kc*4+1][row] = vb.y;
            Bs[kc*4+2][row] = vb.z;
            Bs[kc*4+3][row] = vb.w;
        }
        __syncthreads();

        #pragma unroll
        for (int kk = 0; kk < 16; kk++) {
            float4 a0 = *(const float4*)&As[kk][ty * 4];
            float4 a1 = *(const float4*)&As[kk][64 + ty * 4];
            float4 b0 = *(const float4*)&Bs[kk][tx * 4];
            float4 b1 = *(const float4*)&Bs[kk][64 + tx * 4];
            const float* ap0 = &a0.x;
            const float* ap1 = &a1.x;
            const float* bp0 = &b0.x;
            const float* bp1 = &b1.x;
            #pragma unroll
            for (int i = 0; i < 4; i++)
                #pragma unroll
                for (int j = 0; j < 4; j++) {
                    acc[0][0][i][j] += ap0[i] * bp0[j];
                    acc[0][1][i][j] += ap0[i] * bp1[j];
                    acc[1][0][i][j] += ap1[i] * bp0[j];
                    acc[1][1][i][j] += ap1[i] * bp1[j];
                }
        }
        __syncthreads();
    }

    // Epilogue
    #pragma unroll
    for (int ih = 0; ih < 2; ih++)
        #pragma unroll
        for (int i = 0; i < 4; i++) {
            int row = m0 + ih * 64 + ty * 4 + i;
            #pragma unroll
            for (int jh = 0; jh < 2; jh++) {
                int col = n0 + jh * 64 + tx * 4;
                float4 bb = make_float4(0.f, 0.f, 0.f, 0.f);
                if (bias) bb = *(const float4*)&bias[col];
                float4 o;
                o.x = acc[ih][jh][i][0] * scale + bb.x;
                o.y = acc[ih][jh][i][1] * scale + bb.y;
                o.z = acc[ih][jh][i][2] * scale + bb.z;
                o.w = acc[ih][jh][i][3] * scale + bb.w;
                if (GELU) {
                    o.x = gelu_exact(o.x);
                    o.y = gelu_exact(o.y);
                    o.z = gelu_exact(o.z);
                    o.w = gelu_exact(o.w);
                }
                *(float4*)&C[(long)row * N + col] = o;
            }
        }
}

// ---------------------------------------------------------------------------
// Flash-style causal attention with hopping bias.
// Grid: (S/64, H, B). Block: 256 threads (16x16). 64-row q tile, dh=64.
// Dynamic smem: QT/KT/Vs/PT each [64][68] floats = 69632 bytes.
// ---------------------------------------------------------------------------
#define APAD 68
__global__ __launch_bounds__(256)
void attn_kernel(const float* __restrict__ qkv, const float* __restrict__ hop,
                 float* __restrict__ out)
{
    extern __shared__ float sm[];
    float* QT = sm;                 // QT[d][q]
    float* KT = sm + 64 * APAD;     // KT[d][k]
    float* Vs = sm + 2 * 64 * APAD; // Vs[k][d]
    float* PT = sm + 3 * 64 * APAD; // PT[k][q]

    const int tid = threadIdx.x;
    const int tx  = tid & 15;
    const int ty  = tid >> 4;
    const int qt  = blockIdx.x;
    const int h   = blockIdx.y;
    const int b   = blockIdx.z;
    const int q0  = qt * 64;

    const long rowbase = (long)b * SS * (3 * DD);

    // Load Q tile (transposed into QT)
    #pragma unroll
    for (int l = 0; l < 4; l++) {
        int f  = tid + l * 256;     // 0..1023
        int r  = f >> 4;            // q row 0..63
        int dc = f & 15;            // float4 column
        float4 v = *(const float4*)&qkv[rowbase + (long)(q0 + r) * (3 * DD) + h * DH + dc * 4];
        QT[(dc*4+0) * APAD + r] = v.x;
        QT[(dc*4+1) * APAD + r] = v.y;
        QT[(dc*4+2) * APAD + r] = v.z;
        QT[(dc*4+3) * APAD + r] = v.w;
    }

    float m[4], lsum[4], acc[4][4];
    #pragma unroll
    for (int i = 0; i < 4; i++) {
        m[i] = -1e30f;
        lsum[i] = 0.0f;
        #pragma unroll
        for (int j = 0; j < 4; j++) acc[i][j] = 0.0f;
    }

    const float isq = 0.125f;  // 1/sqrt(dh)
    const long hb = (long)b * SS * SS;

    for (int kt = 0; kt <= qt; kt++) {
        const int k0 = kt * 64;

        // Load K (transposed) and V tiles
        #pragma unroll
        for (int l = 0; l < 4; l++) {
            int f  = tid + l * 256;
            int r  = f >> 4;
            int dc = f & 15;
            long base = rowbase + (long)(k0 + r) * (3 * DD) + h * DH + dc * 4;
            float4 kv = *(const float4*)&qkv[base + DD];
            KT[(dc*4+0) * APAD + r] = kv.x;
            KT[(dc*4+1) * APAD + r] = kv.y;
            KT[(dc*4+2) * APAD + r] = kv.z;
            KT[(dc*4+3) * APAD + r] = kv.w;
            float4 vv = *(const float4*)&qkv[base + 2 * DD];
            *(float4*)&Vs[r * APAD + dc * 4] = vv;
        }
        __syncthreads();

        // S = Q @ K^T  (4x4 per thread)
        float s[4][4];
        #pragma unroll
        for (int i = 0; i < 4; i++)
            #pragma unroll
            for (int j = 0; j < 4; j++) s[i][j] = 0.0f;

        #pragma unroll 16
        for (int d = 0; d < 64; d++) {
            float4 a  = *(const float4*)&QT[d * APAD + ty * 4];
            float4 bv = *(const float4*)&KT[d * APAD + tx * 4];
            const float* ap = &a.x;
            const float* bp = &bv.x;
            #pragma unroll
            for (int i = 0; i < 4; i++)
                #pragma unroll
                for (int j = 0; j < 4; j++)
                    s[i][j] += ap[i] * bp[j];
        }

        // bias + mask + online softmax (per q row; 16 tx threads share a row)
        #pragma unroll
        for (int i = 0; i < 4; i++) {
            const int rg = q0 + ty * 4 + i;
            float4 hv = *(const float4*)&hop[hb + (long)rg * SS + k0 + tx * 4];
            const float* hp = &hv.x;
            float sv[4];
            #pragma unroll
            for (int j = 0; j < 4; j++) {
                sv[j] = s[i][j] * isq + hp[j];
                if (k0 + tx * 4 + j > rg) sv[j] = -1e30f;
            }
            float rm = fmaxf(fmaxf(sv[0], sv[1]), fmaxf(sv[2], sv[3]));
            #pragma unroll
            for (int o = 8; o > 0; o >>= 1)
                rm = fmaxf(rm, __shfl_xor_sync(0xffffffffu, rm, o));

            float nm  = fmaxf(m[i], rm);
            float scl = __expf(m[i] - nm);
            float p[4], rs = 0.0f;
            #pragma unroll
            for (int j = 0; j < 4; j++) {
                p[j] = __expf(sv[j] - nm);
                rs += p[j];
            }
            #pragma unroll
            for (int o = 8; o > 0; o >>= 1)
                rs += __shfl_xor_sync(0xffffffffu, rs, o);

            lsum[i] = lsum[i] * scl + rs;
            m[i]    = nm;
            #pragma unroll
            for (int j = 0; j < 4; j++) acc[i][j] *= scl;
            #pragma unroll
            for (int j = 0; j < 4; j++)
                PT[(tx * 4 + j) * APAD + ty * 4 + i] = p[j];
        }
        __syncthreads();

        // O += P @ V
        #pragma unroll 16
        for (int k = 0; k < 64; k++) {
            float4 a  = *(const float4*)&PT[k * APAD + ty * 4];
            float4 bv = *(const float4*)&Vs[k * APAD + tx * 4];
            const float* ap = &a.x;
            const float* bp = &bv.x;
            #pragma unroll
            for (int i = 0; i < 4; i++)
                #pragma unroll
                for (int j = 0; j < 4; j++)
                    acc[i][j] += ap[i] * bp[j];
        }
        __syncthreads();
    }

    // Write out: [B,S,H*dh]
    #pragma unroll
    for (int i = 0; i < 4; i++) {
        const int rg = q0 + ty * 4 + i;
        const float inv = 1.0f / lsum[i];
        float4 o;
        o.x = acc[i][0] * inv;
        o.y = acc[i][1] * inv;
        o.z = acc[i][2] * inv;
        o.w = acc[i][3] * inv;
        *(float4*)&out[((long)b * SS + rg) * DD + h * DH + tx * 4] = o;
    }
}

// ---------------------------------------------------------------------------
// Fused residual + LayerNorm. One block per row of 1024.
// out = LN(resid + y) * g + beta
// ---------------------------------------------------------------------------
__global__ __launch_bounds__(256)
void ln_kernel(const float* __restrict__ resid, const float* __restrict__ y,
               const float* __restrict__ g, const float* __restrict__ beta,
               float* __restrict__ out)
{
    __shared__ float red[16];
    __shared__ float stats[2];

    const long row = blockIdx.x;
    const int tid  = threadIdx.x;
    const long base = row * DD + tid * 4;

    float4 r  = *(const float4*)&resid[base];
    float4 yv = *(const float4*)&y[base];
    float v0 = r.x + yv.x, v1 = r.y + yv.y, v2 = r.z + yv.z, v3 = r.w + yv.w;

    float s  = v0 + v1 + v2 + v3;
    float ss = v0*v0 + v1*v1 + v2*v2 + v3*v3;
    #pragma unroll
    for (int o = 16; o > 0; o >>= 1) {
        s  += __shfl_xor_sync(0xffffffffu, s, o);
        ss += __shfl_xor_sync(0xffffffffu, ss, o);
    }
    const int warp = tid >> 5;
    if ((tid & 31) == 0) {
        red[warp * 2]     = s;
        red[warp * 2 + 1] = ss;
    }
    __syncthreads();
    if (tid == 0) {
        float ts = 0.f, tss = 0.f;
        #pragma unroll
        for (int w = 0; w < 8; w++) { ts += red[w*2]; tss += red[w*2+1]; }
        float mean = ts * (1.0f / DD);
        float var  = tss * (1.0f / DD) - mean * mean;
        stats[0] = mean;
        stats[1] = rsqrtf(var + 1e-5f);
    }
    __syncthreads();
    const float mean = stats[0];
    const float istd = stats[1];

    float4 gv = *(const float4*)&g[tid * 4];
    float4 bv = *(const float4*)&beta[tid * 4];
    float4 o;
    o.x = (v0 - mean) * istd * gv.x + bv.x;
    o.y = (v1 - mean) * istd * gv.y + bv.y;
    o.z = (v2 - mean) * istd * gv.z + bv.z;
    o.w = (v3 - mean) * istd * gv.w + bv.w;
    *(float4*)&out[base] = o;
}

// ---------------------------------------------------------------------------
// Launcher
// ---------------------------------------------------------------------------
extern "C" void kernel_launch(void* const* d_in, const int* in_sizes, int n_in,
                              void* d_out, int out_size)
{
    const float* x      = (const float*)d_in[0];
    const float* imag   = (const float*)d_in[1];
    const float* w_qkv  = (const float*)d_in[2];
    const float* b_qkv  = (const float*)d_in[3];
    const float* w_o    = (const float*)d_in[4];
    const float* b_o    = (const float*)d_in[5];
    const float* ln1_g  = (const float*)d_in[6];
    const float* ln1_b  = (const float*)d_in[7];
    const float* w1     = (const float*)d_in[8];
    const float* b1     = (const float*)d_in[9];
    const float* w2     = (const float*)d_in[10];
    const float* b2     = (const float*)d_in[11];
    const float* ln2_g  = (const float*)d_in[12];
    const float* ln2_b  = (const float*)d_in[13];
    float* out = (float*)d_out;

    float *qkvp, *hopp, *attnp, *att2p, *x1p, *f1p, *f2p;
    cudaGetSymbolAddress((void**)&qkvp,  g_qkv);
    cudaGetSymbolAddress((void**)&hopp,  g_hop);
    cudaGetSymbolAddress((void**)&attnp, g_attn);
    cudaGetSymbolAddress((void**)&att2p, g_att2);
    cudaGetSymbolAddress((void**)&x1p,   g_x1);
    cudaGetSymbolAddress((void**)&f1p,   g_ff1);
    cudaGetSymbolAddress((void**)&f2p,   g_ff2);

    cudaFuncSetAttribute(attn_kernel,
                         cudaFuncAttributeMaxDynamicSharedMemorySize,
                         4 * 64 * APAD * sizeof(float));

    const int MR = BB * SS;  // 8192 rows

    // 1) hopping[b] = imag[b] @ imag[b]^T / sqrt(D)  (lower-triangular tiles only)
    sgemm_bt<false><<<dim3(SS/128, SS/128, BB), 256>>>(
        imag, imag, nullptr, hopp, SS, SS, DD,
        (long)SS * DD, (long)SS * DD, (long)SS * SS, 0.03125f, 1);

    // 2) QKV projection
    sgemm_bt<false><<<dim3(3*DD/128, MR/128, 1), 256>>>(
        x, w_qkv, b_qkv, qkvp, MR, 3*DD, DD, 0, 0, 0, 1.0f, 0);

    // 3) Causal attention with hopping bias
    attn_kernel<<<dim3(SS/64, HH, BB), 256, 4 * 64 * APAD * sizeof(float)>>>(
        qkvp, hopp, attnp);

    // 4) Output projection
    sgemm_bt<false><<<dim3(DD/128, MR/128, 1), 256>>>(
        attnp, w_o, b_o, att2p, MR, DD, DD, 0, 0, 0, 1.0f, 0);

    // 5) LN1(x + attn_out)
    ln_kernel<<<MR, 256>>>(x, att2p, ln1_g, ln1_b, x1p);

    // 6) FFN1 + exact GELU
    sgemm_bt<true><<<dim3(4*DD/128, MR/128, 1), 256>>>(
        x1p, w1, b1, f1p, MR, 4*DD, DD, 0, 0, 0, 1.0f, 0);

    // 7) FFN2
    sgemm_bt<false><<<dim3(DD/128, MR/128, 1), 256>>>(
        f1p, w2, b2, f2p, MR, DD, 4*DD, 0, 0, 0, 1.0f, 0);

    // 8) LN2(x1 + ffn_out) -> output
    ln_kernel<<<MR, 256>>>(x1p, f2p, ln2_g, ln2_b, out);
}

// round 2
// speedup vs baseline: 2.1469x; 2.1469x over previous
#include <cuda_runtime.h>
#include <cuda_bf16.h>
#include <math.h>

// Problem constants
#define BB 4
#define SS 2048
#define DD 1024
#define HH 16
#define DH 64

// ---------------------------------------------------------------------------
// Scratch (device globals — no runtime allocation allowed)
// ---------------------------------------------------------------------------
__device__ float g_qkv [(long)BB * SS * 3 * DD];   // [B,S,3D]
__device__ float g_hop [(long)BB * SS * SS];       // [B,S,S]
__device__ float g_attn[(long)BB * SS * DD];       // attention output (pre O-proj)
__device__ float g_att2[(long)BB * SS * DD];       // after O-proj
__device__ float g_x1  [(long)BB * SS * DD];       // after LN1
__device__ float g_ff1 [(long)BB * SS * 4 * DD];   // after FFN1+GELU
__device__ float g_ff2 [(long)BB * SS * DD];       // after FFN2

__device__ __forceinline__ float gelu_exact(float x) {
    return 0.5f * x * (1.0f + erff(x * 0.70710678118654752f));
}

__device__ __forceinline__ float to_tf32(float x) {
    asm("cvt.rna.tf32.f32 %0, %0;" : "+f"(x));
    return x;
}

__device__ __forceinline__ void mma_tf32(float* c, const float* a, const float* b) {
    asm volatile(
        "mma.sync.aligned.m16n8k8.row.col.f32.tf32.tf32.f32 "
        "{%0,%1,%2,%3}, {%4,%5,%6,%7}, {%8,%9}, {%0,%1,%2,%3};"
        : "+f"(c[0]), "+f"(c[1]), "+f"(c[2]), "+f"(c[3])
        : "r"(__float_as_uint(a[0])), "r"(__float_as_uint(a[1])),
          "r"(__float_as_uint(a[2])), "r"(__float_as_uint(a[3])),
          "r"(__float_as_uint(b[0])), "r"(__float_as_uint(b[1])));
}

// ---------------------------------------------------------------------------
// TF32 tensor-core GEMM: C[M,N] = scale * (A[M,K] @ B[N,K]^T) + bias[N],
// optional exact GELU. 128x128x32 tiles, 256 threads (8 warps, 2x4 layout,
// each warp a 64x32 output tile via m16n8k8 tf32 mma).
// Requires M%128==0, N%128==0, K%32==0 (true at all call sites).
// causal!=0 => skip tiles with n0 > m0+127 (hopping matrix).
// ---------------------------------------------------------------------------
#define SPAD 36
template<bool GELU>
__global__ __launch_bounds__(256, 2)
void sgemm_bt(const float* __restrict__ A, const float* __restrict__ B,
              const float* __restrict__ bias, float* __restrict__ C,
              int M, int N, int K,
              long sA, long sB, long sC, float scale, int causal)
{
    __shared__ float As[128][SPAD];   // [m][k] tf32 values
    __shared__ float Bs[128][SPAD];   // [n][k] tf32 values

    const int tid  = threadIdx.x;
    const int warp = tid >> 5;
    const int lane = tid & 31;
    const int g    = lane >> 2;   // quad group 0..7
    const int t    = lane & 3;    // thread-in-quad
    const int m0   = blockIdx.y * 128;
    const int n0   = blockIdx.x * 128;

    if (causal && n0 > m0 + 127) return;

    const int z = blockIdx.z;
    A += (long)z * sA;
    B += (long)z * sB;
    C += (long)z * sC;

    const int wm = (warp & 1) * 64;   // warp m offset
    const int wn = (warp >> 1) * 32;  // warp n offset

    float acc[4][4][4];               // [mi][ni][c0..c3]
    #pragma unroll
    for (int mi = 0; mi < 4; mi++)
        #pragma unroll
        for (int ni = 0; ni < 4; ni++)
            #pragma unroll
            for (int c = 0; c < 4; c++)
                acc[mi][ni][c] = 0.0f;

    // Per-thread staging coordinates for the cooperative tile loads:
    // 1024 float4s per 128x32 tile, 4 per thread.
    const int lr = tid >> 3;          // row 0..31 base (advances by 32 per l)
    const int lc = (tid & 7) * 4;     // col 0,4,...,28

    for (int k0 = 0; k0 < K; k0 += 32) {
        #pragma unroll
        for (int l = 0; l < 4; l++) {
            int r = lr + l * 32;
            float4 va = *(const float4*)&A[(long)(m0 + r) * K + k0 + lc];
            As[r][lc+0] = to_tf32(va.x);
            As[r][lc+1] = to_tf32(va.y);
            As[r][lc+2] = to_tf32(va.z);
            As[r][lc+3] = to_tf32(va.w);
            float4 vb = *(const float4*)&B[(long)(n0 + r) * K + k0 + lc];
            Bs[r][lc+0] = to_tf32(vb.x);
            Bs[r][lc+1] = to_tf32(vb.y);
            Bs[r][lc+2] = to_tf32(vb.z);
            Bs[r][lc+3] = to_tf32(vb.w);
        }
        __syncthreads();

        #pragma unroll
        for (int ks = 0; ks < 4; ks++) {
            const int kb = ks * 8;
            float a[4][4], b[4][2];
            #pragma unroll
            for (int mi = 0; mi < 4; mi++) {
                const int row = wm + mi * 16;
                a[mi][0] = As[row + g    ][kb + t    ];
                a[mi][1] = As[row + g + 8][kb + t    ];
                a[mi][2] = As[row + g    ][kb + t + 4];
                a[mi][3] = As[row + g + 8][kb + t + 4];
            }
            #pragma unroll
            for (int ni = 0; ni < 4; ni++) {
                const int col = wn + ni * 8;
                b[ni][0] = Bs[col + g][kb + t    ];
                b[ni][1] = Bs[col + g][kb + t + 4];
            }
            #pragma unroll
            for (int mi = 0; mi < 4; mi++)
                #pragma unroll
                for (int ni = 0; ni < 4; ni++)
                    mma_tf32(acc[mi][ni], a[mi], b[ni]);
        }
        __syncthreads();
    }

    // Epilogue: c0,c1 at (g, 2t),(g, 2t+1); c2,c3 at (g+8, same cols)
    #pragma unroll
    for (int mi = 0; mi < 4; mi++) {
        const int row0 = m0 + wm + mi * 16 + g;
        #pragma unroll
        for (int ni = 0; ni < 4; ni++) {
            const int col = n0 + wn + ni * 8 + 2 * t;
            float bx = 0.0f, by = 0.0f;
            if (bias) { bx = bias[col]; by = bias[col + 1]; }
            float o0 = acc[mi][ni][0] * scale + bx;
            float o1 = acc[mi][ni][1] * scale + by;
            float o2 = acc[mi][ni][2] * scale + bx;
            float o3 = acc[mi][ni][3] * scale + by;
            if (GELU) {
                o0 = gelu_exact(o0); o1 = gelu_exact(o1);
                o2 = gelu_exact(o2); o3 = gelu_exact(o3);
            }
            *(float2*)&C[(long)row0 * N + col]       = make_float2(o0, o1);
            *(float2*)&C[(long)(row0 + 8) * N + col] = make_float2(o2, o3);
        }
    }
}

// ---------------------------------------------------------------------------
// Flash-style causal attention with hopping bias.
// Grid: (S/64, H, B). Block: 256 threads (16x16). 64-row q tile, dh=64.
// Dynamic smem: QT/KT/Vs/PT each [64][68] floats = 69632 bytes.
// ---------------------------------------------------------------------------
#define APAD 68
__global__ __launch_bounds__(256)
void attn_kernel(const float* __restrict__ qkv, const float* __restrict__ hop,
                 float* __restrict__ out)
{
    extern __shared__ float sm[];
    float* QT = sm;                 // QT[d][q]
    float* KT = sm + 64 * APAD;     // KT[d][k]
    float* Vs = sm + 2 * 64 * APAD; // Vs[k][d]
    float* PT = sm + 3 * 64 * APAD; // PT[k][q]

    const int tid = threadIdx.x;
    const int tx  = tid & 15;
    const int ty  = tid >> 4;
    const int qt  = blockIdx.x;
    const int h   = blockIdx.y;
    const int b   = blockIdx.z;
    const int q0  = qt * 64;

    const long rowbase = (long)b * SS * (3 * DD);

    // Load Q tile (transposed into QT)
    #pragma unroll
    for (int l = 0; l < 4; l++) {
        int f  = tid + l * 256;     // 0..1023
        int r  = f >> 4;            // q row 0..63
        int dc = f & 15;            // float4 column
        float4 v = *(const float4*)&qkv[rowbase + (long)(q0 + r) * (3 * DD) + h * DH + dc * 4];
        QT[(dc*4+0) * APAD + r] = v.x;
        QT[(dc*4+1) * APAD + r] = v.y;
        QT[(dc*4+2) * APAD + r] = v.z;
        QT[(dc*4+3) * APAD + r] = v.w;
    }

    float m[4], lsum[4], acc[4][4];
    #pragma unroll
    for (int i = 0; i < 4; i++) {
        m[i] = -1e30f;
        lsum[i] = 0.0f;
        #pragma unroll
        for (int j = 0; j < 4; j++) acc[i][j] = 0.0f;
    }

    const float isq = 0.125f;  // 1/sqrt(dh)
    const long hb = (long)b * SS * SS;

    for (int kt = 0; kt <= qt; kt++) {
        const int k0 = kt * 64;

        // Load K (transposed) and V tiles
        #pragma unroll
        for (int l = 0; l < 4; l++) {
            int f  = tid + l * 256;
            int r  = f >> 4;
            int dc = f & 15;
            long base = rowbase + (long)(k0 + r) * (3 * DD) + h * DH + dc * 4;
            float4 kv = *(const float4*)&qkv[base + DD];
            KT[(dc*4+0) * APAD + r] = kv.x;
            KT[(dc*4+1) * APAD + r] = kv.y;
            KT[(dc*4+2) * APAD + r] = kv.z;
            KT[(dc*4+3) * APAD + r] = kv.w;
            float4 vv = *(const float4*)&qkv[base + 2 * DD];
            *(float4*)&Vs[r * APAD + dc * 4] = vv;
        }
        __syncthreads();

        // S = Q @ K^T  (4x4 per thread)
        float s[4][4];
        #pragma unroll
        for (int i = 0; i < 4; i++)
            #pragma unroll
            for (int j = 0; j < 4; j++) s[i][j] = 0.0f;

        #pragma unroll 16
        for (int d = 0; d < 64; d++) {
            float4 a  = *(const float4*)&QT[d * APAD + ty * 4];
            float4 bv = *(const float4*)&KT[d * APAD + tx * 4];
            const float* ap = &a.x;
            const float* bp = &bv.x;
            #pragma unroll
            for (int i = 0; i < 4; i++)
                #pragma unroll
                for (int j = 0; j < 4; j++)
                    s[i][j] += ap[i] * bp[j];
        }

        // bias + mask + online softmax (per q row; 16 tx threads share a row)
        #pragma unroll
        for (int i = 0; i < 4; i++) {
            const int rg = q0 + ty * 4 + i;
            float4 hv = *(const float4*)&hop[hb + (long)rg * SS + k0 + tx * 4];
            const float* hp = &hv.x;
            float sv[4];
            #pragma unroll
            for (int j = 0; j < 4; j++) {
                sv[j] = s[i][j] * isq + hp[j];
                if (k0 + tx * 4 + j > rg) sv[j] = -1e30f;
            }
            float rm = fmaxf(fmaxf(sv[0], sv[1]), fmaxf(sv[2], sv[3]));
            #pragma unroll
            for (int o = 8; o > 0; o >>= 1)
                rm = fmaxf(rm, __shfl_xor_sync(0xffffffffu, rm, o));

            float nm  = fmaxf(m[i], rm);
            float scl = __expf(m[i] - nm);
            float p[4], rs = 0.0f;
            #pragma unroll
            for (int j = 0; j < 4; j++) {
                p[j] = __expf(sv[j] - nm);
                rs += p[j];
            }
            #pragma unroll
            for (int o = 8; o > 0; o >>= 1)
                rs += __shfl_xor_sync(0xffffffffu, rs, o);

            lsum[i] = lsum[i] * scl + rs;
            m[i]    = nm;
            #pragma unroll
            for (int j = 0; j < 4; j++) acc[i][j] *= scl;
            #pragma unroll
            for (int j = 0; j < 4; j++)
                PT[(tx * 4 + j) * APAD + ty * 4 + i] = p[j];
        }
        __syncthreads();

        // O += P @ V
        #pragma unroll 16
        for (int k = 0; k < 64; k++) {
            float4 a  = *(const float4*)&PT[k * APAD + ty * 4];
            float4 bv = *(const float4*)&Vs[k * APAD + tx * 4];
            const float* ap = &a.x;
            const float* bp = &bv.x;
            #pragma unroll
            for (int i = 0; i < 4; i++)
                #pragma unroll
                for (int j = 0; j < 4; j++)
                    acc[i][j] += ap[i] * bp[j];
        }
        __syncthreads();
    }

    // Write out: [B,S,H*dh]
    #pragma unroll
    for (int i = 0; i < 4; i++) {
        const int rg = q0 + ty * 4 + i;
        const float inv = 1.0f / lsum[i];
        float4 o;
        o.x = acc[i][0] * inv;
        o.y = acc[i][1] * inv;
        o.z = acc[i][2] * inv;
        o.w = acc[i][3] * inv;
        *(float4*)&out[((long)b * SS + rg) * DD + h * DH + tx * 4] = o;
    }
}

// ---------------------------------------------------------------------------
// Fused residual + LayerNorm. One block per row of 1024.
// out = LN(resid + y) * g + beta
// ---------------------------------------------------------------------------
__global__ __launch_bounds__(256)
void ln_kernel(const float* __restrict__ resid, const float* __restrict__ y,
               const float* __restrict__ g, const float* __restrict__ beta,
               float* __restrict__ out)
{
    __shared__ float red[16];
    __shared__ float stats[2];

    const long row = blockIdx.x;
    const int tid  = threadIdx.x;
    const long base = row * DD + tid * 4;

    float4 r  = *(const float4*)&resid[base];
    float4 yv = *(const float4*)&y[base];
    float v0 = r.x + yv.x, v1 = r.y + yv.y, v2 = r.z + yv.z, v3 = r.w + yv.w;

    float s  = v0 + v1 + v2 + v3;
    float ss = v0*v0 + v1*v1 + v2*v2 + v3*v3;
    #pragma unroll
    for (int o = 16; o > 0; o >>= 1) {
        s  += __shfl_xor_sync(0xffffffffu, s, o);
        ss += __shfl_xor_sync(0xffffffffu, ss, o);
    }
    const int warp = tid >> 5;
    if ((tid & 31) == 0) {
        red[warp * 2]     = s;
        red[warp * 2 + 1] = ss;
    }
    __syncthreads();
    if (tid == 0) {
        float ts = 0.f, tss = 0.f;
        #pragma unroll
        for (int w = 0; w < 8; w++) { ts += red[w*2]; tss += red[w*2+1]; }
        float mean = ts * (1.0f / DD);
        float var  = tss * (1.0f / DD) - mean * mean;
        stats[0] = mean;
        stats[1] = rsqrtf(var + 1e-5f);
    }
    __syncthreads();
    const float mean = stats[0];
    const float istd = stats[1];

    float4 gv = *(const float4*)&g[tid * 4];
    float4 bv = *(const float4*)&beta[tid * 4];
    float4 o;
    o.x = (v0 - mean) * istd * gv.x + bv.x;
    o.y = (v1 - mean) * istd * gv.y + bv.y;
    o.z = (v2 - mean) * istd * gv.z + bv.z;
    o.w = (v3 - mean) * istd * gv.w + bv.w;
    *(float4*)&out[base] = o;
}

// ---------------------------------------------------------------------------
// Launcher
// ---------------------------------------------------------------------------
extern "C" void kernel_launch(void* const* d_in, const int* in_sizes, int n_in,
                              void* d_out, int out_size)
{
    const float* x      = (const float*)d_in[0];
    const float* imag   = (const float*)d_in[1];
    const float* w_qkv  = (const float*)d_in[2];
    const float* b_qkv  = (const float*)d_in[3];
    const float* w_o    = (const float*)d_in[4];
    const float* b_o    = (const float*)d_in[5];
    const float* ln1_g  = (const float*)d_in[6];
    const float* ln1_b  = (const float*)d_in[7];
    const float* w1     = (const float*)d_in[8];
    const float* b1     = (const float*)d_in[9];
    const float* w2     = (const float*)d_in[10];
    const float* b2     = (const float*)d_in[11];
    const float* ln2_g  = (const float*)d_in[12];
    const float* ln2_b  = (const float*)d_in[13];
    float* out = (float*)d_out;

    float *qkvp, *hopp, *attnp, *att2p, *x1p, *f1p, *f2p;
    cudaGetSymbolAddress((void**)&qkvp,  g_qkv);
    cudaGetSymbolAddress((void**)&hopp,  g_hop);
    cudaGetSymbolAddress((void**)&attnp, g_attn);
    cudaGetSymbolAddress((void**)&att2p, g_att2);
    cudaGetSymbolAddress((void**)&x1p,   g_x1);
    cudaGetSymbolAddress((void**)&f1p,   g_ff1);
    cudaGetSymbolAddress((void**)&f2p,   g_ff2);

    cudaFuncSetAttribute(attn_kernel,
                         cudaFuncAttributeMaxDynamicSharedMemorySize,
                         4 * 64 * APAD * sizeof(float));

    const int MR = BB * SS;  // 8192 rows

    // 1) hopping[b] = imag[b] @ imag[b]^T / sqrt(D)  (lower-triangular tiles only)
    sgemm_bt<false><<<dim3(SS/128, SS/128, BB), 256>>>(
        imag, imag, nullptr, hopp, SS, SS, DD,
        (long)SS * DD, (long)SS * DD, (long)SS * SS, 0.03125f, 1);

    // 2) QKV projection
    sgemm_bt<false><<<dim3(3*DD/128, MR/128, 1), 256>>>(
        x, w_qkv, b_qkv, qkvp, MR, 3*DD, DD, 0, 0, 0, 1.0f, 0);

    // 3) Causal attention with hopping bias
    attn_kernel<<<dim3(SS/64, HH, BB), 256, 4 * 64 * APAD * sizeof(float)>>>(
        qkvp, hopp, attnp);

    // 4) Output projection
    sgemm_bt<false><<<dim3(DD/128, MR/128, 1), 256>>>(
        attnp, w_o, b_o, att2p, MR, DD, DD, 0, 0, 0, 1.0f, 0);

    // 5) LN1(x + attn_out)
    ln_kernel<<<MR, 256>>>(x, att2p, ln1_g, ln1_b, x1p);

    // 6) FFN1 + exact GELU
    sgemm_bt<true><<<dim3(4*DD/128, MR/128, 1), 256>>>(
        x1p, w1, b1, f1p, MR, 4*DD, DD, 0, 0, 0, 1.0f, 0);

    // 7) FFN2
    sgemm_bt<false><<<dim3(DD/128, MR/128, 1), 256>>>(
        f1p, w2, b2, f2p, MR, DD, 4*DD, 0, 0, 0, 1.0f, 0);

    // 8) LN2(x1 + ffn_out) -> output
    ln_kernel<<<MR, 256>>>(x1p, f2p, ln2_g, ln2_b, out);
}